// round 1
// baseline (speedup 1.0000x reference)
#include <cuda_runtime.h>
#include <math.h>

#define S 618
#define B 16
#define EPS 1e-6f

// scratch: normalized q and k multivectors, [side][b][n][8]
__device__ float g_qk[2][B * S * 8];

// ---------------------------------------------------------------------------
// Kernel A: fused mv_linear + bias + grade-norm normalize for q and k.
// Block: 128 threads = 8 n-values x 16 batches. grid = (ceil(S/8), 2 sides).
// Each thread accumulates all 8 blade components for one (b, n).
// ---------------------------------------------------------------------------
constexpr int TN = 8;
constexpr int MC = 16;

__global__ __launch_bounds__(128) void qk_kernel(
    const float* __restrict__ x,
    const float* __restrict__ qw, const float* __restrict__ qb,
    const float* __restrict__ kw, const float* __restrict__ kb,
    const float* __restrict__ a)
{
    const int side = blockIdx.y;
    const float* __restrict__ w    = side ? kw : qw;
    const float* __restrict__ bias = side ? kb : qb;
    float* __restrict__ out = &g_qk[side][0];

    const int n0  = blockIdx.x * TN;
    const int tid = threadIdx.x;
    const int nl  = tid & 7;        // local n
    const int bl  = tid >> 3;       // batch
    const int n   = n0 + nl;

    __shared__ float4 sw[TN][MC + 1];        // w[n][m][g0..g3], padded row
    __shared__ float  sx[B][MC * 8 + 4];     // x[b][m][i], padded row

    float acc0 = 0.f, acc1 = 0.f, acc2 = 0.f, acc3 = 0.f;
    float acc4 = 0.f, acc5 = 0.f, acc6 = 0.f, acc7 = 0.f;

    for (int m0 = 0; m0 < S; m0 += MC) {
        // --- load w chunk: TN*MC float4 = 128 -> one per thread
        {
            int wn = tid / MC;
            int wm = tid % MC;
            int gm = m0 + wm;
            int gn = n0 + wn;
            float4 v = make_float4(0.f, 0.f, 0.f, 0.f);
            if (gn < S && gm < S)
                v = *reinterpret_cast<const float4*>(w + ((size_t)gn * S + gm) * 4);
            sw[wn][wm] = v;
        }
        // --- load x chunk: B*MC*8 floats = 512 float4 -> 4 per thread
        #pragma unroll
        for (int r = 0; r < 4; r++) {
            int v   = tid + r * 128;      // 0..511
            int xb  = v >> 5;             // 32 float4 per batch-chunk
            int off = v & 31;             // float4 index inside [MC][8]
            int mm  = off >> 1;
            int hi  = (off & 1) * 4;
            int xm  = m0 + mm;
            float4 val = make_float4(0.f, 0.f, 0.f, 0.f);
            if (xm < S)
                val = *reinterpret_cast<const float4*>(x + ((size_t)xb * S + xm) * 8 + hi);
            *reinterpret_cast<float4*>(&sx[xb][mm * 8 + hi]) = val;
        }
        __syncthreads();

        #pragma unroll
        for (int mm = 0; mm < MC; mm++) {
            float4 wv = sw[nl][mm];
            float4 x0 = *reinterpret_cast<float4*>(&sx[bl][mm * 8]);
            float4 x1 = *reinterpret_cast<float4*>(&sx[bl][mm * 8 + 4]);
            acc0 += x0.x * wv.x;
            acc1 += x0.y * wv.y;
            acc2 += x0.z * wv.y;
            acc3 += x0.w * wv.y;
            acc4 += x1.x * wv.z;
            acc5 += x1.y * wv.z;
            acc6 += x1.z * wv.z;
            acc7 += x1.w * wv.w;
        }
        __syncthreads();
    }

    if (n < S) {
        acc0 += bias[n];   // bias goes into scalar blade only

        // per-grade L2 norms
        float nm0 = fabsf(acc0);
        float nm1 = sqrtf(acc1 * acc1 + acc2 * acc2 + acc3 * acc3);
        float nm2 = sqrtf(acc4 * acc4 + acc5 * acc5 + acc6 * acc6);
        float nm3 = fabsf(acc7);

        const float* ap = a + (size_t)n * 4;
        float s0 = 1.f / (1.f + expf(-ap[0]));
        float s1 = 1.f / (1.f + expf(-ap[1]));
        float s2 = 1.f / (1.f + expf(-ap[2]));
        float s3 = 1.f / (1.f + expf(-ap[3]));

        float d0 = 1.f / (s0 * (nm0 - 1.f) + 1.f + EPS);
        float d1 = 1.f / (s1 * (nm1 - 1.f) + 1.f + EPS);
        float d2 = 1.f / (s2 * (nm2 - 1.f) + 1.f + EPS);
        float d3 = 1.f / (s3 * (nm3 - 1.f) + 1.f + EPS);

        float* o = out + ((size_t)bl * S + n) * 8;
        float4 o0 = make_float4(acc0 * d0, acc1 * d1, acc2 * d1, acc3 * d1);
        float4 o1 = make_float4(acc4 * d2, acc5 * d2, acc6 * d2, acc7 * d3);
        *reinterpret_cast<float4*>(o)     = o0;
        *reinterpret_cast<float4*>(o + 4) = o1;
    }
}

// ---------------------------------------------------------------------------
// Kernel B: pairwise geometric product.
// out[b,m,n,j] = sum_{i,k} q[b,m,i] C[i,j,k] k[b,n,k]
// Cl(3,0), blade order [1, e1, e2, e3, e12, e13, e23, e123] — 64 signed FMAs,
// table hardcoded (derived from the reference sign algorithm).
// Block: 256 threads = 16m x 16n tile. grid = (39, 39, 16).
// ---------------------------------------------------------------------------
__global__ __launch_bounds__(256) void gp_kernel(float* __restrict__ out)
{
    const int b  = blockIdx.z;
    const int m0 = blockIdx.y * 16;
    const int n0 = blockIdx.x * 16;
    const int tid = threadIdx.x;

    __shared__ float sq[16][8];
    __shared__ float sk[16][8];

    if (tid < 32) {
        int r = tid & 15;
        bool is_q = tid < 16;
        int row = (is_q ? m0 : n0) + r;
        const float* src = &g_qk[is_q ? 0 : 1][((size_t)b * S + row) * 8];
        float4 v0 = make_float4(0.f, 0.f, 0.f, 0.f), v1 = v0;
        if (row < S) {
            v0 = *reinterpret_cast<const float4*>(src);
            v1 = *reinterpret_cast<const float4*>(src + 4);
        }
        float* dst = is_q ? sq[r] : sk[r];
        *reinterpret_cast<float4*>(dst)     = v0;
        *reinterpret_cast<float4*>(dst + 4) = v1;
    }
    __syncthreads();

    const int nl = tid & 15;
    const int ml = tid >> 4;
    const int m = m0 + ml;
    const int n = n0 + nl;
    if (m >= S || n >= S) return;

    float q0 = sq[ml][0], q1 = sq[ml][1], q2 = sq[ml][2], q3 = sq[ml][3];
    float q4 = sq[ml][4], q5 = sq[ml][5], q6 = sq[ml][6], q7 = sq[ml][7];
    float k0 = sk[nl][0], k1 = sk[nl][1], k2 = sk[nl][2], k3 = sk[nl][3];
    float k4 = sk[nl][4], k5 = sk[nl][5], k6 = sk[nl][6], k7 = sk[nl][7];

    float o0, o1, o2, o3, o4, o5, o6, o7;
    // i = 0 (scalar)
    o0 = q0 * k0; o1 = q0 * k1; o2 = q0 * k2; o3 = q0 * k3;
    o4 = q0 * k4; o5 = q0 * k5; o6 = q0 * k6; o7 = q0 * k7;
    // i = 1 (e1)
    o1 += q1 * k0; o0 += q1 * k1; o4 += q1 * k2; o5 += q1 * k3;
    o2 += q1 * k4; o3 += q1 * k5; o7 += q1 * k6; o6 += q1 * k7;
    // i = 2 (e2)
    o2 += q2 * k0; o4 -= q2 * k1; o0 += q2 * k2; o6 += q2 * k3;
    o1 -= q2 * k4; o7 -= q2 * k5; o3 += q2 * k6; o5 -= q2 * k7;
    // i = 3 (e3)
    o3 += q3 * k0; o5 -= q3 * k1; o6 -= q3 * k2; o0 += q3 * k3;
    o7 += q3 * k4; o1 -= q3 * k5; o2 -= q3 * k6; o4 += q3 * k7;
    // i = 4 (e12)
    o4 += q4 * k0; o2 -= q4 * k1; o1 += q4 * k2; o7 += q4 * k3;
    o0 -= q4 * k4; o6 -= q4 * k5; o5 += q4 * k6; o3 -= q4 * k7;
    // i = 5 (e13)
    o5 += q5 * k0; o3 -= q5 * k1; o7 -= q5 * k2; o1 += q5 * k3;
    o6 += q5 * k4; o0 -= q5 * k5; o4 -= q5 * k6; o2 += q5 * k7;
    // i = 6 (e23)
    o6 += q6 * k0; o7 += q6 * k1; o3 -= q6 * k2; o2 += q6 * k3;
    o5 -= q6 * k4; o4 += q6 * k5; o0 -= q6 * k6; o1 -= q6 * k7;
    // i = 7 (e123)
    o7 += q7 * k0; o6 += q7 * k1; o5 -= q7 * k2; o4 += q7 * k3;
    o3 -= q7 * k4; o2 += q7 * k5; o1 -= q7 * k6; o0 -= q7 * k7;

    float* dst = out + (((size_t)b * S + m) * S + n) * 8;
    *reinterpret_cast<float4*>(dst)     = make_float4(o0, o1, o2, o3);
    *reinterpret_cast<float4*>(dst + 4) = make_float4(o4, o5, o6, o7);
}

// ---------------------------------------------------------------------------
extern "C" void kernel_launch(void* const* d_in, const int* in_sizes, int n_in,
                              void* d_out, int out_size)
{
    const float* x  = (const float*)d_in[0];
    const float* qw = (const float*)d_in[1];
    const float* qb = (const float*)d_in[2];
    const float* kw = (const float*)d_in[3];
    const float* kb = (const float*)d_in[4];
    const float* a  = (const float*)d_in[5];
    float* out = (float*)d_out;

    dim3 gridA((S + TN - 1) / TN, 2);
    qk_kernel<<<gridA, 128>>>(x, qw, qb, kw, kb, a);

    dim3 gridB((S + 15) / 16, (S + 15) / 16, B);
    gp_kernel<<<gridB, 256>>>(out);
}

// round 2
// speedup vs baseline: 1.4394x; 1.4394x over previous
#include <cuda_runtime.h>
#include <math.h>

#define S 618
#define B 16
#define EPS 1e-6f

// scratch: normalized q and k multivectors, [side][b][n][8]
__device__ float g_qk[2][B * S * 8];

// ---------------------------------------------------------------------------
// Kernel A: fused mv_linear + bias + grade-norm normalize for q and k.
// Block = 256 threads = 4 m-groups x (8 n x 8 b). Each group accumulates a
// strided quarter of the m-reduction; smem reduction + normalize at the end.
// grid = (78 n-blocks, 2 batch-halves, 2 sides) = 312 blocks.
// ---------------------------------------------------------------------------
constexpr int MC  = 16;   // m per chunk
constexpr int NG  = 4;    // m-groups per block
constexpr int TNQ = 8;    // n per block
constexpr int TBQ = 8;    // batches per block

__global__ __launch_bounds__(256) void qk_kernel(
    const float* __restrict__ x,
    const float* __restrict__ qw, const float* __restrict__ qb,
    const float* __restrict__ kw, const float* __restrict__ kb,
    const float* __restrict__ a)
{
    const int side   = blockIdx.z;
    const int bsplit = blockIdx.y;
    const float* __restrict__ w    = side ? kw : qw;
    const float* __restrict__ bias = side ? kb : qb;
    float* __restrict__ out = &g_qk[side][0];

    const int n0  = blockIdx.x * TNQ;
    const int tid = threadIdx.x;
    const int g   = tid >> 6;          // m-group 0..3
    const int lid = tid & 63;
    const int nl  = lid & 7;           // local n
    const int bl  = lid >> 3;          // local batch 0..7
    const int n   = n0 + nl;
    const int b   = bsplit * TBQ + bl;

    __shared__ float4 sw[NG][TNQ][MC + 1];        // w[n][m][g0..g3]
    __shared__ float  sx[NG][TBQ][MC * 8 + 4];    // x[b][m][i]
    __shared__ float  sred[NG][64][8];

    float acc0 = 0.f, acc1 = 0.f, acc2 = 0.f, acc3 = 0.f;
    float acc4 = 0.f, acc5 = 0.f, acc6 = 0.f, acc7 = 0.f;

    // group g handles m0 = g*MC + j*NG*MC ; max j such that 48 + 64*9 < 618+64
    #pragma unroll 1
    for (int j = 0; j < 10; j++) {
        const int m0 = g * MC + j * (NG * MC);
        const bool act = (m0 < S);

        // --- load w chunk: TNQ*MC = 128 float4 per group, 2 per thread
        #pragma unroll
        for (int r = 0; r < 2; r++) {
            int idx = lid + r * 64;
            int wn = idx >> 4;
            int wm = idx & 15;
            int gm = m0 + wm;
            int gn = n0 + wn;
            float4 v = make_float4(0.f, 0.f, 0.f, 0.f);
            if (act && gn < S && gm < S)
                v = *reinterpret_cast<const float4*>(w + ((size_t)gn * S + gm) * 4);
            sw[g][wn][wm] = v;
        }
        // --- load x chunk: TBQ*MC*8 floats = 256 float4 per group, 4 per thread
        #pragma unroll
        for (int r = 0; r < 4; r++) {
            int idx = lid + r * 64;
            int xb  = idx >> 5;          // 0..7
            int off = idx & 31;
            int mm  = off >> 1;
            int hi  = (off & 1) * 4;
            int gm  = m0 + mm;
            int gb  = bsplit * TBQ + xb;
            float4 v = make_float4(0.f, 0.f, 0.f, 0.f);
            if (act && gm < S)
                v = *reinterpret_cast<const float4*>(x + ((size_t)gb * S + gm) * 8 + hi);
            *reinterpret_cast<float4*>(&sx[g][xb][mm * 8 + hi]) = v;
        }
        __syncthreads();

        if (act) {
            #pragma unroll
            for (int mm = 0; mm < MC; mm++) {
                float4 wv = sw[g][nl][mm];
                float4 x0 = *reinterpret_cast<float4*>(&sx[g][bl][mm * 8]);
                float4 x1 = *reinterpret_cast<float4*>(&sx[g][bl][mm * 8 + 4]);
                acc0 += x0.x * wv.x;
                acc1 += x0.y * wv.y;
                acc2 += x0.z * wv.y;
                acc3 += x0.w * wv.y;
                acc4 += x1.x * wv.z;
                acc5 += x1.y * wv.z;
                acc6 += x1.z * wv.z;
                acc7 += x1.w * wv.w;
            }
        }
        __syncthreads();
    }

    // --- cross-group reduction
    *reinterpret_cast<float4*>(&sred[g][lid][0]) = make_float4(acc0, acc1, acc2, acc3);
    *reinterpret_cast<float4*>(&sred[g][lid][4]) = make_float4(acc4, acc5, acc6, acc7);
    __syncthreads();

    if (g == 0 && n < S) {
        float r0 = 0.f, r1 = 0.f, r2 = 0.f, r3 = 0.f;
        float r4 = 0.f, r5 = 0.f, r6 = 0.f, r7 = 0.f;
        #pragma unroll
        for (int gg = 0; gg < NG; gg++) {
            float4 v0 = *reinterpret_cast<float4*>(&sred[gg][lid][0]);
            float4 v1 = *reinterpret_cast<float4*>(&sred[gg][lid][4]);
            r0 += v0.x; r1 += v0.y; r2 += v0.z; r3 += v0.w;
            r4 += v1.x; r5 += v1.y; r6 += v1.z; r7 += v1.w;
        }
        r0 += bias[n];   // bias goes into scalar blade only

        float nm0 = fabsf(r0);
        float nm1 = sqrtf(r1 * r1 + r2 * r2 + r3 * r3);
        float nm2 = sqrtf(r4 * r4 + r5 * r5 + r6 * r6);
        float nm3 = fabsf(r7);

        const float* ap = a + (size_t)n * 4;
        float s0 = 1.f / (1.f + expf(-ap[0]));
        float s1 = 1.f / (1.f + expf(-ap[1]));
        float s2 = 1.f / (1.f + expf(-ap[2]));
        float s3 = 1.f / (1.f + expf(-ap[3]));

        float d0 = 1.f / (s0 * (nm0 - 1.f) + 1.f + EPS);
        float d1 = 1.f / (s1 * (nm1 - 1.f) + 1.f + EPS);
        float d2 = 1.f / (s2 * (nm2 - 1.f) + 1.f + EPS);
        float d3 = 1.f / (s3 * (nm3 - 1.f) + 1.f + EPS);

        float* o = out + ((size_t)b * S + n) * 8;
        *reinterpret_cast<float4*>(o)     = make_float4(r0 * d0, r1 * d1, r2 * d1, r3 * d1);
        *reinterpret_cast<float4*>(o + 4) = make_float4(r4 * d2, r5 * d2, r6 * d2, r7 * d3);
    }
}

// ---------------------------------------------------------------------------
// Kernel B: pairwise geometric product.
// out[b,m,n,j] = sum_{i,k} q[b,m,i] C[i,j,k] k[b,n,k]  (Cl(3,0), 64 signed FMA)
// Tile: 16 m x 32 n per block, 256 threads, each thread computes (m, n) and
// (m, n+16). smem rows padded to 12 floats (48B) -> conflict-free LDS.128.
// ---------------------------------------------------------------------------
#define GP_PAD 12

__device__ __forceinline__ void geo_prod(
    float q0, float q1, float q2, float q3,
    float q4, float q5, float q6, float q7,
    const float* __restrict__ k, float* __restrict__ o)
{
    float k0 = k[0], k1 = k[1], k2 = k[2], k3 = k[3];
    float k4 = k[4], k5 = k[5], k6 = k[6], k7 = k[7];
    float o0, o1, o2, o3, o4, o5, o6, o7;
    // i = 0 (scalar)
    o0 = q0 * k0; o1 = q0 * k1; o2 = q0 * k2; o3 = q0 * k3;
    o4 = q0 * k4; o5 = q0 * k5; o6 = q0 * k6; o7 = q0 * k7;
    // i = 1 (e1)
    o1 += q1 * k0; o0 += q1 * k1; o4 += q1 * k2; o5 += q1 * k3;
    o2 += q1 * k4; o3 += q1 * k5; o7 += q1 * k6; o6 += q1 * k7;
    // i = 2 (e2)
    o2 += q2 * k0; o4 -= q2 * k1; o0 += q2 * k2; o6 += q2 * k3;
    o1 -= q2 * k4; o7 -= q2 * k5; o3 += q2 * k6; o5 -= q2 * k7;
    // i = 3 (e3)
    o3 += q3 * k0; o5 -= q3 * k1; o6 -= q3 * k2; o0 += q3 * k3;
    o7 += q3 * k4; o1 -= q3 * k5; o2 -= q3 * k6; o4 += q3 * k7;
    // i = 4 (e12)
    o4 += q4 * k0; o2 -= q4 * k1; o1 += q4 * k2; o7 += q4 * k3;
    o0 -= q4 * k4; o6 -= q4 * k5; o5 += q4 * k6; o3 -= q4 * k7;
    // i = 5 (e13)
    o5 += q5 * k0; o3 -= q5 * k1; o7 -= q5 * k2; o1 += q5 * k3;
    o6 += q5 * k4; o0 -= q5 * k5; o4 -= q5 * k6; o2 += q5 * k7;
    // i = 6 (e23)
    o6 += q6 * k0; o7 += q6 * k1; o3 -= q6 * k2; o2 += q6 * k3;
    o5 -= q6 * k4; o4 += q6 * k5; o0 -= q6 * k6; o1 -= q6 * k7;
    // i = 7 (e123)
    o7 += q7 * k0; o6 += q7 * k1; o5 -= q7 * k2; o4 += q7 * k3;
    o3 -= q7 * k4; o2 += q7 * k5; o1 -= q7 * k6; o0 -= q7 * k7;
    o[0] = o0; o[1] = o1; o[2] = o2; o[3] = o3;
    o[4] = o4; o[5] = o5; o[6] = o6; o[7] = o7;
}

__global__ __launch_bounds__(256) void gp_kernel(float* __restrict__ out)
{
    const int b  = blockIdx.z;
    const int m0 = blockIdx.y * 16;
    const int n0 = blockIdx.x * 32;
    const int tid = threadIdx.x;

    __shared__ float sq[16][GP_PAD];
    __shared__ float sk[32][GP_PAD];

    if (tid < 48) {
        bool is_q = tid < 16;
        int r   = is_q ? tid : (tid - 16);
        int row = (is_q ? m0 : n0) + r;
        const float* src = &g_qk[is_q ? 0 : 1][((size_t)b * S + row) * 8];
        float4 v0 = make_float4(0.f, 0.f, 0.f, 0.f), v1 = v0;
        if (row < S) {
            v0 = *reinterpret_cast<const float4*>(src);
            v1 = *reinterpret_cast<const float4*>(src + 4);
        }
        float* dst = is_q ? sq[r] : sk[r];
        *reinterpret_cast<float4*>(dst)     = v0;
        *reinterpret_cast<float4*>(dst + 4) = v1;
    }
    __syncthreads();

    const int nl = tid & 15;
    const int ml = tid >> 4;
    const int m  = m0 + ml;
    const int na = n0 + nl;
    const int nb = n0 + 16 + nl;

    // q registers (broadcast within half-warp)
    float4 qa = *reinterpret_cast<float4*>(&sq[ml][0]);
    float4 qb = *reinterpret_cast<float4*>(&sq[ml][4]);

    float kA[8], kB[8];
    {
        float4 a0 = *reinterpret_cast<float4*>(&sk[nl][0]);
        float4 a1 = *reinterpret_cast<float4*>(&sk[nl][4]);
        float4 b0 = *reinterpret_cast<float4*>(&sk[nl + 16][0]);
        float4 b1 = *reinterpret_cast<float4*>(&sk[nl + 16][4]);
        kA[0] = a0.x; kA[1] = a0.y; kA[2] = a0.z; kA[3] = a0.w;
        kA[4] = a1.x; kA[5] = a1.y; kA[6] = a1.z; kA[7] = a1.w;
        kB[0] = b0.x; kB[1] = b0.y; kB[2] = b0.z; kB[3] = b0.w;
        kB[4] = b1.x; kB[5] = b1.y; kB[6] = b1.z; kB[7] = b1.w;
    }

    float oA[8], oB[8];
    geo_prod(qa.x, qa.y, qa.z, qa.w, qb.x, qb.y, qb.z, qb.w, kA, oA);
    geo_prod(qa.x, qa.y, qa.z, qa.w, qb.x, qb.y, qb.z, qb.w, kB, oB);

    if (m < S) {
        float* base = out + (((size_t)b * S + m) * S) * 8;
        if (na < S) {
            float* d = base + (size_t)na * 8;
            *reinterpret_cast<float4*>(d)     = make_float4(oA[0], oA[1], oA[2], oA[3]);
            *reinterpret_cast<float4*>(d + 4) = make_float4(oA[4], oA[5], oA[6], oA[7]);
        }
        if (nb < S) {
            float* d = base + (size_t)nb * 8;
            *reinterpret_cast<float4*>(d)     = make_float4(oB[0], oB[1], oB[2], oB[3]);
            *reinterpret_cast<float4*>(d + 4) = make_float4(oB[4], oB[5], oB[6], oB[7]);
        }
    }
}

// ---------------------------------------------------------------------------
extern "C" void kernel_launch(void* const* d_in, const int* in_sizes, int n_in,
                              void* d_out, int out_size)
{
    const float* x  = (const float*)d_in[0];
    const float* qw = (const float*)d_in[1];
    const float* qb = (const float*)d_in[2];
    const float* kw = (const float*)d_in[3];
    const float* kb = (const float*)d_in[4];
    const float* a  = (const float*)d_in[5];
    float* out = (float*)d_out;

    dim3 gridA((S + TNQ - 1) / TNQ, 2, 2);
    qk_kernel<<<gridA, 256>>>(x, qw, qb, kw, kb, a);

    dim3 gridB((S + 31) / 32, (S + 15) / 16, B);
    gp_kernel<<<gridB, 256>>>(out);
}

// round 3
// speedup vs baseline: 1.6291x; 1.1318x over previous
#include <cuda_runtime.h>
#include <math.h>

#define S 618
#define B 16
#define EPS 1e-6f

// scratch: normalized q and k multivectors, [side][b*S + n][8]
__device__ float g_qk[2][B * S * 8];
// split-K partials: [side][quarter][b*S + n][8]
__device__ float g_part[2][4][B * S * 8];

// ---------------------------------------------------------------------------
// cp.async helpers
// ---------------------------------------------------------------------------
__device__ __forceinline__ void cp_async16(void* smem_dst, const void* gsrc, bool pred) {
    unsigned saddr = (unsigned)__cvta_generic_to_shared(smem_dst);
    int sz = pred ? 16 : 0;
    asm volatile("cp.async.ca.shared.global [%0], [%1], 16, %2;\n"
                 :: "r"(saddr), "l"(gsrc), "r"(sz));
}
__device__ __forceinline__ void cp_commit() {
    asm volatile("cp.async.commit_group;\n");
}

// ---------------------------------------------------------------------------
// Kernel A1: partial mv_linear. grid = (78 n-blocks, 4 m-quarters, 2 sides),
// block = 128 threads = 8 n x 16 b. Each block reduces 160 m values
// (10 chunks of 16) with a cp.async double-buffered pipeline, then writes an
// 8-float partial per (b, n) to g_part.
// ---------------------------------------------------------------------------
constexpr int MCQ = 16;   // m per chunk
constexpr int NCH = 10;   // chunks per quarter (160 m)
constexpr int TNQ = 8;    // n per block

__global__ __launch_bounds__(128) void qk_partial_kernel(
    const float* __restrict__ x,
    const float* __restrict__ qw,
    const float* __restrict__ kw)
{
    const int side = blockIdx.z;
    const int mq   = blockIdx.y;
    const float* __restrict__ w = side ? kw : qw;

    const int n0  = blockIdx.x * TNQ;
    const int tid = threadIdx.x;
    const int nl  = tid & 7;          // local n
    const int bl  = tid >> 3;         // batch 0..15
    const int n   = n0 + nl;
    const int mbaseQ = mq * (MCQ * NCH);

    __shared__ float4 sw[2][TNQ][MCQ + 1];
    __shared__ float  sx[2][B][MCQ * 8 + 4];

    // per-thread prefetch descriptors:
    // w: 1 float4: wn = tid>>4, wm = tid&15
    const int wn = tid >> 4;
    const int wm = tid & 15;
    const int gn = n0 + wn;

    float acc0 = 0.f, acc1 = 0.f, acc2 = 0.f, acc3 = 0.f;
    float acc4 = 0.f, acc5 = 0.f, acc6 = 0.f, acc7 = 0.f;

    // prefetch routine as a lambda-free macro-style block
    auto prefetch = [&](int j) {
        const int mb  = mbaseQ + j * MCQ;
        const int buf = j & 1;
        {   // w chunk
            int gm = mb + wm;
            bool p = (gn < S) && (gm < S);
            const float* src = w + (p ? ((size_t)gn * S + gm) * 4 : 0);
            cp_async16(&sw[buf][wn][wm], src, p);
        }
        #pragma unroll
        for (int r = 0; r < 4; r++) {   // x chunk: 512 float4, 4 per thread
            int idx  = tid + r * 128;
            int xb   = idx >> 5;
            int off  = idx & 31;
            int mm   = off >> 1;
            int half = (off & 1) * 4;
            int gm   = mb + mm;
            bool p = (gm < S);
            const float* src = x + (p ? ((size_t)xb * S + gm) * 8 + half : 0);
            cp_async16(&sx[buf][xb][mm * 8 + half], src, p);
        }
        cp_commit();
    };

    prefetch(0);

    #pragma unroll 1
    for (int j = 0; j < NCH; j++) {
        if (j + 1 < NCH) {
            prefetch(j + 1);
            asm volatile("cp.async.wait_group 1;\n");
        } else {
            asm volatile("cp.async.wait_group 0;\n");
        }
        __syncthreads();

        const int buf = j & 1;
        #pragma unroll
        for (int mm = 0; mm < MCQ; mm++) {
            float4 wv = sw[buf][nl][mm];
            float4 x0 = *reinterpret_cast<const float4*>(&sx[buf][bl][mm * 8]);
            float4 x1 = *reinterpret_cast<const float4*>(&sx[buf][bl][mm * 8 + 4]);
            acc0 += x0.x * wv.x;
            acc1 += x0.y * wv.y;
            acc2 += x0.z * wv.y;
            acc3 += x0.w * wv.y;
            acc4 += x1.x * wv.z;
            acc5 += x1.y * wv.z;
            acc6 += x1.z * wv.z;
            acc7 += x1.w * wv.w;
        }
        __syncthreads();
    }

    if (n < S) {
        float* o = &g_part[side][mq][((size_t)bl * S + n) * 8];
        *reinterpret_cast<float4*>(o)     = make_float4(acc0, acc1, acc2, acc3);
        *reinterpret_cast<float4*>(o + 4) = make_float4(acc4, acc5, acc6, acc7);
    }
}

// ---------------------------------------------------------------------------
// Kernel A2: reduce 4 partials + bias + grade-norm normalize -> g_qk.
// One thread per (side, b, n). 2*16*618 = 19776 threads.
// ---------------------------------------------------------------------------
__global__ __launch_bounds__(256) void qk_finalize_kernel(
    const float* __restrict__ qb, const float* __restrict__ kb,
    const float* __restrict__ a)
{
    int gid = blockIdx.x * 256 + threadIdx.x;
    const int total = 2 * B * S;
    if (gid >= total) return;
    const int n    = gid % S;
    const int b    = (gid / S) % B;
    const int side = gid / (S * B);
    const float* __restrict__ bias = side ? kb : qb;

    const size_t off = ((size_t)b * S + n) * 8;
    float r0 = 0.f, r1 = 0.f, r2 = 0.f, r3 = 0.f;
    float r4 = 0.f, r5 = 0.f, r6 = 0.f, r7 = 0.f;
    #pragma unroll
    for (int p = 0; p < 4; p++) {
        const float* src = &g_part[side][p][off];
        float4 v0 = *reinterpret_cast<const float4*>(src);
        float4 v1 = *reinterpret_cast<const float4*>(src + 4);
        r0 += v0.x; r1 += v0.y; r2 += v0.z; r3 += v0.w;
        r4 += v1.x; r5 += v1.y; r6 += v1.z; r7 += v1.w;
    }
    r0 += bias[n];

    float nm0 = fabsf(r0);
    float nm1 = sqrtf(r1 * r1 + r2 * r2 + r3 * r3);
    float nm2 = sqrtf(r4 * r4 + r5 * r5 + r6 * r6);
    float nm3 = fabsf(r7);

    const float* ap = a + (size_t)n * 4;
    float s0 = 1.f / (1.f + expf(-ap[0]));
    float s1 = 1.f / (1.f + expf(-ap[1]));
    float s2 = 1.f / (1.f + expf(-ap[2]));
    float s3 = 1.f / (1.f + expf(-ap[3]));

    float d0 = 1.f / (s0 * (nm0 - 1.f) + 1.f + EPS);
    float d1 = 1.f / (s1 * (nm1 - 1.f) + 1.f + EPS);
    float d2 = 1.f / (s2 * (nm2 - 1.f) + 1.f + EPS);
    float d3 = 1.f / (s3 * (nm3 - 1.f) + 1.f + EPS);

    float* o = &g_qk[side][off];
    *reinterpret_cast<float4*>(o)     = make_float4(r0 * d0, r1 * d1, r2 * d1, r3 * d1);
    *reinterpret_cast<float4*>(o + 4) = make_float4(r4 * d2, r5 * d2, r6 * d2, r7 * d3);
}

// ---------------------------------------------------------------------------
// Kernel B: pairwise geometric product with lane-paired blade split.
// Block = 256 threads (8 warps), grid = (ceil(S/8)=78 m-chunks, 16 b).
// All of k[b] staged in smem once. Warp w owns m row m0+w; per iteration a
// lane pair (2l, 2l+1) handles one n: even lane -> blades 0-3, odd -> 4-7.
// Every STG.128 is a dense 512B/warp write (full sectors).
// ---------------------------------------------------------------------------
#define SKN 624   // padded n count

__global__ __launch_bounds__(256) void gp_kernel(float* __restrict__ out)
{
    const int b  = blockIdx.y;
    const int m0 = blockIdx.x * 8;
    const int tid  = threadIdx.x;
    const int lane = tid & 31;
    const int w    = tid >> 5;

    __shared__ float4 sk_lo[SKN];
    __shared__ float4 sk_hi[SKN];
    __shared__ float4 sq[8][2];

    // stage k[b] (618 rows x 8 floats) as SoA float4
    const float* kbase = &g_qk[1][(size_t)b * S * 8];
    #pragma unroll
    for (int it = 0; it < 5; it++) {
        int idx = tid + it * 256;           // 0..1279, need 1248
        if (idx < 2 * SKN) {
            int nn   = idx >> 1;
            int half = idx & 1;
            float4 v = make_float4(0.f, 0.f, 0.f, 0.f);
            if (nn < S)
                v = *reinterpret_cast<const float4*>(kbase + (size_t)nn * 8 + half * 4);
            (half ? sk_hi : sk_lo)[nn] = v;
        }
    }
    // stage q rows m0..m0+7
    if (tid < 16) {
        int r = tid >> 1, half = tid & 1;
        int row = m0 + r;
        float4 v = make_float4(0.f, 0.f, 0.f, 0.f);
        if (row < S)
            v = *reinterpret_cast<const float4*>(&g_qk[0][((size_t)b * S + row) * 8 + half * 4]);
        sq[r][half] = v;
    }
    __syncthreads();

    const int m = m0 + w;
    if (m >= S) return;

    const float4 ql = sq[w][0];
    const float4 qh = sq[w][1];
    const float q0 = ql.x, q1 = ql.y, q2 = ql.z, q3 = ql.w;
    const float q4 = qh.x, q5 = qh.y, q6 = qh.z, q7 = qh.w;

    const bool  odd   = lane & 1;
    const int   nlane = lane >> 1;           // 0..15
    float* const obase = out + (((size_t)b * S + m) * S) * 8 + lane * 4;

    // 618 = 38*16 + 10 : 38 full iterations + 1 guarded
    #pragma unroll 2
    for (int j = 0; j < 38; j++) {
        const int n = j * 16 + nlane;
        float4 kl = sk_lo[n];
        float4 kh = sk_hi[n];
        float k0 = kl.x, k1 = kl.y, k2 = kl.z, k3 = kl.w;
        float k4 = kh.x, k5 = kh.y, k6 = kh.z, k7 = kh.w;

        float4 o;
        if (!odd) {
            o.x =  q0*k0 + q1*k1 + q2*k2 + q3*k3 - q4*k4 - q5*k5 - q6*k6 - q7*k7;
            o.y =  q0*k1 + q1*k0 - q2*k4 - q3*k5 + q4*k2 + q5*k3 - q6*k7 - q7*k6;
            o.z =  q0*k2 + q1*k4 + q2*k0 - q3*k6 - q4*k1 + q5*k7 + q6*k3 + q7*k5;
            o.w =  q0*k3 + q1*k5 + q2*k6 + q3*k0 - q4*k7 - q5*k1 - q6*k2 - q7*k4;
        } else {
            o.x =  q0*k4 + q1*k2 - q2*k1 + q3*k7 + q4*k0 - q5*k6 + q6*k5 + q7*k3;
            o.y =  q0*k5 + q1*k3 - q2*k7 - q3*k1 + q4*k6 + q5*k0 - q6*k4 - q7*k2;
            o.z =  q0*k6 + q1*k7 + q2*k3 - q3*k2 - q4*k5 + q5*k4 + q6*k0 + q7*k1;
            o.w =  q0*k7 + q1*k6 - q2*k5 + q3*k4 + q4*k3 - q5*k2 + q6*k1 + q7*k0;
        }
        *reinterpret_cast<float4*>(obase + (size_t)j * 128) = o;
    }
    {   // tail: j = 38, n = 608 + nlane, valid for n < 618
        const int n = 608 + nlane;
        if (n < S) {
            float4 kl = sk_lo[n];
            float4 kh = sk_hi[n];
            float k0 = kl.x, k1 = kl.y, k2 = kl.z, k3 = kl.w;
            float k4 = kh.x, k5 = kh.y, k6 = kh.z, k7 = kh.w;
            float4 o;
            if (!odd) {
                o.x =  q0*k0 + q1*k1 + q2*k2 + q3*k3 - q4*k4 - q5*k5 - q6*k6 - q7*k7;
                o.y =  q0*k1 + q1*k0 - q2*k4 - q3*k5 + q4*k2 + q5*k3 - q6*k7 - q7*k6;
                o.z =  q0*k2 + q1*k4 + q2*k0 - q3*k6 - q4*k1 + q5*k7 + q6*k3 + q7*k5;
                o.w =  q0*k3 + q1*k5 + q2*k6 + q3*k0 - q4*k7 - q5*k1 - q6*k2 - q7*k4;
            } else {
                o.x =  q0*k4 + q1*k2 - q2*k1 + q3*k7 + q4*k0 - q5*k6 + q6*k5 + q7*k3;
                o.y =  q0*k5 + q1*k3 - q2*k7 - q3*k1 + q4*k6 + q5*k0 - q6*k4 - q7*k2;
                o.z =  q0*k6 + q1*k7 + q2*k3 - q3*k2 - q4*k5 + q5*k4 + q6*k0 + q7*k1;
                o.w =  q0*k7 + q1*k6 - q2*k5 + q3*k4 + q4*k3 - q5*k2 + q6*k1 + q7*k0;
            }
            *reinterpret_cast<float4*>(obase + (size_t)38 * 128) = o;
        }
    }
}

// ---------------------------------------------------------------------------
extern "C" void kernel_launch(void* const* d_in, const int* in_sizes, int n_in,
                              void* d_out, int out_size)
{
    const float* x  = (const float*)d_in[0];
    const float* qw = (const float*)d_in[1];
    const float* qb = (const float*)d_in[2];
    const float* kw = (const float*)d_in[3];
    const float* kb = (const float*)d_in[4];
    const float* a  = (const float*)d_in[5];
    float* out = (float*)d_out;

    dim3 gridA1((S + TNQ - 1) / TNQ, 4, 2);
    qk_partial_kernel<<<gridA1, 128>>>(x, qw, kw);

    int totalA2 = 2 * B * S;
    qk_finalize_kernel<<<(totalA2 + 255) / 256, 256>>>(qb, kb, a);

    dim3 gridB((S + 7) / 8, B);
    gp_kernel<<<gridB, 256>>>(out);
}

// round 5
// speedup vs baseline: 1.7100x; 1.0497x over previous
#include <cuda_runtime.h>
#include <math.h>

#define S 618
#define B 16
#define EPS 1e-6f

typedef unsigned long long u64;

// scratch: normalized q and k multivectors, [side][b*S + n][8]
__device__ float g_qk[2][B * S * 8];
// split-K partials: [side][slice][b*S + n][8]
__device__ float g_part[2][8][B * S * 8];

// ---------------------------------------------------------------------------
// f32x2 helpers
// ---------------------------------------------------------------------------
__device__ __forceinline__ u64 pk2(float lo, float hi) {
    u64 r; asm("mov.b64 %0, {%1, %2};" : "=l"(r) : "f"(lo), "f"(hi)); return r;
}
__device__ __forceinline__ u64 mul2(u64 a, u64 b) {
    u64 d; asm("mul.rn.f32x2 %0, %1, %2;" : "=l"(d) : "l"(a), "l"(b)); return d;
}
__device__ __forceinline__ u64 fma2(u64 a, u64 b, u64 c) {
    u64 d; asm("fma.rn.f32x2 %0, %1, %2, %3;" : "=l"(d) : "l"(a), "l"(b), "l"(c)); return d;
}
__device__ __forceinline__ void up2(u64 v, float& lo, float& hi) {
    asm("mov.b64 {%0, %1}, %2;" : "=f"(lo), "=f"(hi) : "l"(v));
}

// ---------------------------------------------------------------------------
// cp.async helpers
// ---------------------------------------------------------------------------
__device__ __forceinline__ void cp_async16(void* smem_dst, const void* gsrc, bool pred) {
    unsigned saddr = (unsigned)__cvta_generic_to_shared(smem_dst);
    int sz = pred ? 16 : 0;   // sz=0 -> zero-fill 16B
    asm volatile("cp.async.ca.shared.global [%0], [%1], 16, %2;\n"
                 :: "r"(saddr), "l"(gsrc), "r"(sz));
}
__device__ __forceinline__ void cp_commit() {
    asm volatile("cp.async.commit_group;\n");
}

// ---------------------------------------------------------------------------
// Kernel A1: partial mv_linear, splitK = 8.
// grid = (78 n-blocks, 8 m-slices, 2 sides) = 1248 blocks, 128 threads.
// Slice s processes chunks c = s + 8j (j = 0..4), chunk = 16 m values.
// Out-of-range chunks/elements are zero-filled via cp.async predication.
// ---------------------------------------------------------------------------
constexpr int MCQ = 16;   // m per chunk
constexpr int NCH = 5;    // chunks per slice
constexpr int TNQ = 8;    // n per block

__global__ __launch_bounds__(128) void qk_partial_kernel(
    const float* __restrict__ x,
    const float* __restrict__ qw,
    const float* __restrict__ kw)
{
    const int side  = blockIdx.z;
    const int slice = blockIdx.y;
    const float* __restrict__ w = side ? kw : qw;

    const int n0  = blockIdx.x * TNQ;
    const int tid = threadIdx.x;
    const int nl  = tid & 7;          // local n
    const int bl  = tid >> 3;         // batch 0..15
    const int n   = n0 + nl;

    __shared__ float4 sw[2][TNQ][MCQ + 1];
    __shared__ float  sx[2][B][MCQ * 8 + 4];

    const int wn = tid >> 4;
    const int wm = tid & 15;
    const int gn = n0 + wn;

    float acc0 = 0.f, acc1 = 0.f, acc2 = 0.f, acc3 = 0.f;
    float acc4 = 0.f, acc5 = 0.f, acc6 = 0.f, acc7 = 0.f;

    auto prefetch = [&](int j) {
        const int mb  = (slice + 8 * j) * MCQ;
        const int buf = j & 1;
        {   // w chunk
            int gm = mb + wm;
            bool p = (gn < S) && (gm < S);
            const float* src = w + (p ? ((size_t)gn * S + gm) * 4 : 0);
            cp_async16(&sw[buf][wn][wm], src, p);
        }
        #pragma unroll
        for (int r = 0; r < 4; r++) {   // x chunk: 512 float4, 4 per thread
            int idx  = tid + r * 128;
            int xb   = idx >> 5;
            int off  = idx & 31;
            int mm   = off >> 1;
            int half = (off & 1) * 4;
            int gm   = mb + mm;
            bool p = (gm < S);
            const float* src = x + (p ? ((size_t)xb * S + gm) * 8 + half : 0);
            cp_async16(&sx[buf][xb][mm * 8 + half], src, p);
        }
        cp_commit();
    };

    prefetch(0);

    #pragma unroll 1
    for (int j = 0; j < NCH; j++) {
        if (j + 1 < NCH) {
            prefetch(j + 1);
            asm volatile("cp.async.wait_group 1;\n");
        } else {
            asm volatile("cp.async.wait_group 0;\n");
        }
        __syncthreads();

        const int buf = j & 1;
        #pragma unroll
        for (int mm = 0; mm < MCQ; mm++) {
            float4 wv = sw[buf][nl][mm];
            float4 x0 = *reinterpret_cast<const float4*>(&sx[buf][bl][mm * 8]);
            float4 x1 = *reinterpret_cast<const float4*>(&sx[buf][bl][mm * 8 + 4]);
            acc0 += x0.x * wv.x;
            acc1 += x0.y * wv.y;
            acc2 += x0.z * wv.y;
            acc3 += x0.w * wv.y;
            acc4 += x1.x * wv.z;
            acc5 += x1.y * wv.z;
            acc6 += x1.z * wv.z;
            acc7 += x1.w * wv.w;
        }
        __syncthreads();
    }

    if (n < S) {
        float* o = &g_part[side][slice][((size_t)bl * S + n) * 8];
        *reinterpret_cast<float4*>(o)     = make_float4(acc0, acc1, acc2, acc3);
        *reinterpret_cast<float4*>(o + 4) = make_float4(acc4, acc5, acc6, acc7);
    }
}

// ---------------------------------------------------------------------------
// Kernel A2: reduce 8 partials + bias + grade-norm normalize -> g_qk.
// ---------------------------------------------------------------------------
__global__ __launch_bounds__(256) void qk_finalize_kernel(
    const float* __restrict__ qb, const float* __restrict__ kb,
    const float* __restrict__ a)
{
    int gid = blockIdx.x * 256 + threadIdx.x;
    const int total = 2 * B * S;
    if (gid >= total) return;
    const int n    = gid % S;
    const int b    = (gid / S) % B;
    const int side = gid / (S * B);
    const float* __restrict__ bias = side ? kb : qb;

    const size_t off = ((size_t)b * S + n) * 8;
    float r0 = 0.f, r1 = 0.f, r2 = 0.f, r3 = 0.f;
    float r4 = 0.f, r5 = 0.f, r6 = 0.f, r7 = 0.f;
    #pragma unroll
    for (int p = 0; p < 8; p++) {
        const float* src = &g_part[side][p][off];
        float4 v0 = *reinterpret_cast<const float4*>(src);
        float4 v1 = *reinterpret_cast<const float4*>(src + 4);
        r0 += v0.x; r1 += v0.y; r2 += v0.z; r3 += v0.w;
        r4 += v1.x; r5 += v1.y; r6 += v1.z; r7 += v1.w;
    }
    r0 += bias[n];

    float nm0 = fabsf(r0);
    float nm1 = sqrtf(r1 * r1 + r2 * r2 + r3 * r3);
    float nm2 = sqrtf(r4 * r4 + r5 * r5 + r6 * r6);
    float nm3 = fabsf(r7);

    const float* ap = a + (size_t)n * 4;
    float s0 = 1.f / (1.f + expf(-ap[0]));
    float s1 = 1.f / (1.f + expf(-ap[1]));
    float s2 = 1.f / (1.f + expf(-ap[2]));
    float s3 = 1.f / (1.f + expf(-ap[3]));

    float d0 = 1.f / (s0 * (nm0 - 1.f) + 1.f + EPS);
    float d1 = 1.f / (s1 * (nm1 - 1.f) + 1.f + EPS);
    float d2 = 1.f / (s2 * (nm2 - 1.f) + 1.f + EPS);
    float d3 = 1.f / (s3 * (nm3 - 1.f) + 1.f + EPS);

    float* o = &g_qk[side][off];
    *reinterpret_cast<float4*>(o)     = make_float4(r0 * d0, r1 * d1, r2 * d1, r3 * d1);
    *reinterpret_cast<float4*>(o + 4) = make_float4(r4 * d2, r5 * d2, r6 * d2, r7 * d3);
}

// ---------------------------------------------------------------------------
// Kernel B: pairwise geometric product, uniform-FMA + f32x2 over m-pairs.
//
// Even lanes (jhalf=0) use k directly and compute blades 0-3.
// Odd lanes (jhalf=1) use k' = k * (-e123)  (e123 central, e123^2 = -1):
//   q * (k * (-w)) = (q*k) * (-w), whose blades 0-3 are (o7, o6, -o5, o4).
// Both k variants pre-staged in smem -> the 32-term FMA body is IDENTICAL
// for all lanes (no divergence). f32x2 packs rows (m, m+1) per warp.
// Blades 0-3 Cayley columns (verified):
//   o0 = q0k0 +q1k1 +q2k2 +q3k3 -q4k4 -q5k5 -q6k6 -q7k7
//   o1 = q1k0 +q0k1 +q4k2 +q5k3 -q2k4 -q3k5 -q7k6 -q6k7
//   o2 = q2k0 -q4k1 +q0k2 +q6k3 +q1k4 +q7k5 -q3k6 +q5k7
//   o3 = q3k0 -q5k1 -q6k2 +q0k3 -q7k4 +q1k5 +q2k6 -q4k7
// ---------------------------------------------------------------------------
#define SKN 624

__global__ __launch_bounds__(256) void gp_kernel(float* __restrict__ out)
{
    const int b  = blockIdx.y;
    const int m0 = blockIdx.x * 16;
    const int tid  = threadIdx.x;
    const int lane = tid & 31;
    const int w    = tid >> 5;

    __shared__ float4 sk_e_lo[SKN], sk_e_hi[SKN];   // k as-is
    __shared__ float4 sk_o_lo[SKN], sk_o_hi[SKN];   // k * (-e123)
    __shared__ float4 sq[16][2];

    // stage k[b]: both variants
    const float* kbase = &g_qk[1][(size_t)b * S * 8];
    for (int r = tid; r < SKN; r += 256) {
        float4 kl = make_float4(0.f, 0.f, 0.f, 0.f), kh = kl;
        if (r < S) {
            kl = *reinterpret_cast<const float4*>(kbase + (size_t)r * 8);
            kh = *reinterpret_cast<const float4*>(kbase + (size_t)r * 8 + 4);
        }
        sk_e_lo[r] = kl;
        sk_e_hi[r] = kh;
        // k' = k*(-e123) = (k7, k6, -k5, k4, -k3, k2, -k1, -k0)
        sk_o_lo[r] = make_float4( kh.w,  kh.z, -kh.y,  kh.x);
        sk_o_hi[r] = make_float4(-kl.w,  kl.z, -kl.y, -kl.x);
    }
    // stage q rows m0..m0+15
    if (tid < 32) {
        int r = tid >> 1, half = tid & 1;
        int row = m0 + r;
        float4 v = make_float4(0.f, 0.f, 0.f, 0.f);
        if (row < S)
            v = *reinterpret_cast<const float4*>(&g_qk[0][((size_t)b * S + row) * 8 + half * 4]);
        sq[r][half] = v;
    }
    __syncthreads();

    const int m = m0 + 2 * w;
    if (m >= S) return;
    const bool has2 = (m + 1 < S);

    // pack q pairs (m in lo, m+1 in hi); row m+1 staged as zeros if OOB
    float4 qlA = sq[2 * w][0],     qhA = sq[2 * w][1];
    float4 qlB = sq[2 * w + 1][0], qhB = sq[2 * w + 1][1];
    u64 qp0 = pk2(qlA.x, qlB.x);
    u64 qp1 = pk2(qlA.y, qlB.y), qn1 = pk2(-qlA.y, -qlB.y);
    u64 qp2 = pk2(qlA.z, qlB.z), qn2 = pk2(-qlA.z, -qlB.z);
    u64 qp3 = pk2(qlA.w, qlB.w), qn3 = pk2(-qlA.w, -qlB.w);
    u64 qp4 = pk2(qhA.x, qhB.x), qn4 = pk2(-qhA.x, -qhB.x);
    u64 qp5 = pk2(qhA.y, qhB.y), qn5 = pk2(-qhA.y, -qhB.y);
    u64 qp6 = pk2(qhA.z, qhB.z), qn6 = pk2(-qhA.z, -qhB.z);
    u64 qp7 = pk2(qhA.w, qhB.w), qn7 = pk2(-qhA.w, -qhB.w);

    const int  jhalf = lane & 1;
    const int  nlane = lane >> 1;
    const float4* __restrict__ klp = jhalf ? sk_o_lo : sk_e_lo;
    const float4* __restrict__ khp = jhalf ? sk_o_hi : sk_e_hi;

    float* const rowA = out + (((size_t)b * S + m) * S) * 8 + jhalf * 4;
    float* const rowB = rowA + (size_t)S * 8;

    auto body = [&](int n) {
        float4 kl = klp[n];
        float4 kh = khp[n];
        u64 kd, o0, o1, o2, o3;
        kd = pk2(kl.x, kl.x);   // k0
        o0 = mul2(qp0, kd); o1 = mul2(qp1, kd); o2 = mul2(qp2, kd); o3 = mul2(qp3, kd);
        kd = pk2(kl.y, kl.y);   // k1
        o0 = fma2(qp1, kd, o0); o1 = fma2(qp0, kd, o1); o2 = fma2(qn4, kd, o2); o3 = fma2(qn5, kd, o3);
        kd = pk2(kl.z, kl.z);   // k2
        o0 = fma2(qp2, kd, o0); o1 = fma2(qp4, kd, o1); o2 = fma2(qp0, kd, o2); o3 = fma2(qn6, kd, o3);
        kd = pk2(kl.w, kl.w);   // k3
        o0 = fma2(qp3, kd, o0); o1 = fma2(qp5, kd, o1); o2 = fma2(qp6, kd, o2); o3 = fma2(qp0, kd, o3);
        kd = pk2(kh.x, kh.x);   // k4
        o0 = fma2(qn4, kd, o0); o1 = fma2(qn2, kd, o1); o2 = fma2(qp1, kd, o2); o3 = fma2(qn7, kd, o3);
        kd = pk2(kh.y, kh.y);   // k5
        o0 = fma2(qn5, kd, o0); o1 = fma2(qn3, kd, o1); o2 = fma2(qp7, kd, o2); o3 = fma2(qp1, kd, o3);
        kd = pk2(kh.z, kh.z);   // k6
        o0 = fma2(qn6, kd, o0); o1 = fma2(qn7, kd, o1); o2 = fma2(qn3, kd, o2); o3 = fma2(qp2, kd, o3);
        kd = pk2(kh.w, kh.w);   // k7
        o0 = fma2(qn7, kd, o0); o1 = fma2(qn6, kd, o1); o2 = fma2(qp5, kd, o2); o3 = fma2(qn4, kd, o3);

        float a0, b0, a1, b1, a2, b2, a3, b3;
        up2(o0, a0, b0); up2(o1, a1, b1); up2(o2, a2, b2); up2(o3, a3, b3);

        // even lanes: (r0,r1,r2,r3) = (o0..o3)
        // odd lanes:  (r0,r1,r2,r3) = (o7, o6, -o5, o4) -> store (o4..o7) = (r3,-r2,r1,r0)
        float4 vA = jhalf ? make_float4(a3, -a2, a1, a0) : make_float4(a0, a1, a2, a3);
        float4 vB = jhalf ? make_float4(b3, -b2, b1, b0) : make_float4(b0, b1, b2, b3);

        *reinterpret_cast<float4*>(rowA + (size_t)n * 8) = vA;
        if (has2)
            *reinterpret_cast<float4*>(rowB + (size_t)n * 8) = vB;
    };

    #pragma unroll 2
    for (int j = 0; j < 38; j++)
        body(j * 16 + nlane);
    {   // tail: n = 608 + nlane, valid while n < 618
        const int n = 608 + nlane;
        if (n < S) body(n);
    }
}

// ---------------------------------------------------------------------------
extern "C" void kernel_launch(void* const* d_in, const int* in_sizes, int n_in,
                              void* d_out, int out_size)
{
    const float* x  = (const float*)d_in[0];
    const float* qw = (const float*)d_in[1];
    const float* qb = (const float*)d_in[2];
    const float* kw = (const float*)d_in[3];
    const float* kb = (const float*)d_in[4];
    const float* a  = (const float*)d_in[5];
    float* out = (float*)d_out;

    dim3 gridA1((S + TNQ - 1) / TNQ, 8, 2);
    qk_partial_kernel<<<gridA1, 128>>>(x, qw, kw);

    int totalA2 = 2 * B * S;
    qk_finalize_kernel<<<(totalA2 + 255) / 256, 256>>>(qb, kb, a);

    dim3 gridB((S + 15) / 16, B);
    gp_kernel<<<gridB, 256>>>(out);
}

// round 6
// speedup vs baseline: 1.9228x; 1.1244x over previous
#include <cuda_runtime.h>
#include <math.h>

#define S 618
#define B 16
#define EPS 1e-6f

typedef unsigned long long u64;

// scratch: normalized q and k multivectors, [side][b*S + n][8]
__device__ float g_qk[2][B * S * 8];
// split-K partials: [side][slice][b*S + n][8]
__device__ float g_part[2][8][B * S * 8];

// ---------------------------------------------------------------------------
// f32x2 helpers
// ---------------------------------------------------------------------------
__device__ __forceinline__ u64 pk2(float lo, float hi) {
    u64 r; asm("mov.b64 %0, {%1, %2};" : "=l"(r) : "f"(lo), "f"(hi)); return r;
}
__device__ __forceinline__ u64 mul2(u64 a, u64 b) {
    u64 d; asm("mul.rn.f32x2 %0, %1, %2;" : "=l"(d) : "l"(a), "l"(b)); return d;
}
__device__ __forceinline__ u64 fma2(u64 a, u64 b, u64 c) {
    u64 d; asm("fma.rn.f32x2 %0, %1, %2, %3;" : "=l"(d) : "l"(a), "l"(b), "l"(c)); return d;
}
__device__ __forceinline__ void up2(u64 v, float& lo, float& hi) {
    asm("mov.b64 {%0, %1}, %2;" : "=f"(lo), "=f"(hi) : "l"(v));
}

// ---------------------------------------------------------------------------
// cp.async helpers
// ---------------------------------------------------------------------------
__device__ __forceinline__ void cp_async16(void* smem_dst, const void* gsrc, bool pred) {
    unsigned saddr = (unsigned)__cvta_generic_to_shared(smem_dst);
    int sz = pred ? 16 : 0;   // sz=0 -> zero-fill 16B
    asm volatile("cp.async.ca.shared.global [%0], [%1], 16, %2;\n"
                 :: "r"(saddr), "l"(gsrc), "r"(sz));
}
__device__ __forceinline__ void cp_commit() {
    asm volatile("cp.async.commit_group;\n");
}

// ---------------------------------------------------------------------------
// Kernel A1: partial mv_linear, splitK = 8, register-tiled 2 n per thread.
// Block 256 = 16 b x 16 nt; thread owns (b, n0+nt) and (b, n0+16+nt),
// 16 accumulators. grid = (20 n-tiles(32), 8 m-slices, 2 sides) = 320 blocks.
// Slice s processes chunks c = s + 8j (j = 0..4), chunk = 16 m values.
// ---------------------------------------------------------------------------
constexpr int MCQ = 16;   // m per chunk
constexpr int NCH = 5;    // chunks per slice
constexpr int TNB = 32;   // n per block

__global__ __launch_bounds__(256) void qk_partial_kernel(
    const float* __restrict__ x,
    const float* __restrict__ qw,
    const float* __restrict__ kw)
{
    const int side  = blockIdx.z;
    const int slice = blockIdx.y;
    const float* __restrict__ w = side ? kw : qw;

    const int n0  = blockIdx.x * TNB;
    const int tid = threadIdx.x;
    const int nt  = tid & 15;         // local n within 16
    const int bt  = tid >> 4;         // batch 0..15
    const int na  = n0 + nt;
    const int nb  = n0 + 16 + nt;

    __shared__ float4 sw[2][TNB][MCQ + 1];
    __shared__ float  sx[2][B][MCQ * 8 + 4];

    float aA0 = 0.f, aA1 = 0.f, aA2 = 0.f, aA3 = 0.f;
    float aA4 = 0.f, aA5 = 0.f, aA6 = 0.f, aA7 = 0.f;
    float aB0 = 0.f, aB1 = 0.f, aB2 = 0.f, aB3 = 0.f;
    float aB4 = 0.f, aB5 = 0.f, aB6 = 0.f, aB7 = 0.f;

    auto prefetch = [&](int j) {
        const int mb  = (slice + 8 * j) * MCQ;
        const int buf = j & 1;
        #pragma unroll
        for (int r = 0; r < 2; r++) {   // w: 32n x 16m float4 = 512, 2/thread
            int idx = tid + r * 256;
            int wn = idx >> 4;
            int wm = idx & 15;
            int gn = n0 + wn;
            int gm = mb + wm;
            bool p = (gn < S) && (gm < S);
            const float* src = w + (p ? ((size_t)gn * S + gm) * 4 : 0);
            cp_async16(&sw[buf][wn][wm], src, p);
        }
        #pragma unroll
        for (int r = 0; r < 2; r++) {   // x: 512 float4, 2/thread
            int idx  = tid + r * 256;
            int xb   = idx >> 5;
            int off  = idx & 31;
            int mm   = off >> 1;
            int half = (off & 1) * 4;
            int gm   = mb + mm;
            bool p = (gm < S);
            const float* src = x + (p ? ((size_t)xb * S + gm) * 8 + half : 0);
            cp_async16(&sx[buf][xb][mm * 8 + half], src, p);
        }
        cp_commit();
    };

    prefetch(0);

    #pragma unroll 1
    for (int j = 0; j < NCH; j++) {
        if (j + 1 < NCH) {
            prefetch(j + 1);
            asm volatile("cp.async.wait_group 1;\n");
        } else {
            asm volatile("cp.async.wait_group 0;\n");
        }
        __syncthreads();

        const int buf = j & 1;
        #pragma unroll
        for (int mm = 0; mm < MCQ; mm++) {
            float4 wa = sw[buf][nt][mm];
            float4 wb = sw[buf][nt + 16][mm];
            float4 x0 = *reinterpret_cast<const float4*>(&sx[buf][bt][mm * 8]);
            float4 x1 = *reinterpret_cast<const float4*>(&sx[buf][bt][mm * 8 + 4]);
            aA0 += x0.x * wa.x;
            aA1 += x0.y * wa.y;
            aA2 += x0.z * wa.y;
            aA3 += x0.w * wa.y;
            aA4 += x1.x * wa.z;
            aA5 += x1.y * wa.z;
            aA6 += x1.z * wa.z;
            aA7 += x1.w * wa.w;
            aB0 += x0.x * wb.x;
            aB1 += x0.y * wb.y;
            aB2 += x0.z * wb.y;
            aB3 += x0.w * wb.y;
            aB4 += x1.x * wb.z;
            aB5 += x1.y * wb.z;
            aB6 += x1.z * wb.z;
            aB7 += x1.w * wb.w;
        }
        __syncthreads();
    }

    if (na < S) {
        float* o = &g_part[side][slice][((size_t)bt * S + na) * 8];
        *reinterpret_cast<float4*>(o)     = make_float4(aA0, aA1, aA2, aA3);
        *reinterpret_cast<float4*>(o + 4) = make_float4(aA4, aA5, aA6, aA7);
    }
    if (nb < S) {
        float* o = &g_part[side][slice][((size_t)bt * S + nb) * 8];
        *reinterpret_cast<float4*>(o)     = make_float4(aB0, aB1, aB2, aB3);
        *reinterpret_cast<float4*>(o + 4) = make_float4(aB4, aB5, aB6, aB7);
    }
}

// ---------------------------------------------------------------------------
// Kernel A2: reduce 8 partials + bias + grade-norm normalize -> g_qk.
// ---------------------------------------------------------------------------
__global__ __launch_bounds__(256) void qk_finalize_kernel(
    const float* __restrict__ qb, const float* __restrict__ kb,
    const float* __restrict__ a)
{
    int gid = blockIdx.x * 256 + threadIdx.x;
    const int total = 2 * B * S;
    if (gid >= total) return;
    const int n    = gid % S;
    const int b    = (gid / S) % B;
    const int side = gid / (S * B);
    const float* __restrict__ bias = side ? kb : qb;

    const size_t off = ((size_t)b * S + n) * 8;
    float r0 = 0.f, r1 = 0.f, r2 = 0.f, r3 = 0.f;
    float r4 = 0.f, r5 = 0.f, r6 = 0.f, r7 = 0.f;
    #pragma unroll
    for (int p = 0; p < 8; p++) {
        const float* src = &g_part[side][p][off];
        float4 v0 = *reinterpret_cast<const float4*>(src);
        float4 v1 = *reinterpret_cast<const float4*>(src + 4);
        r0 += v0.x; r1 += v0.y; r2 += v0.z; r3 += v0.w;
        r4 += v1.x; r5 += v1.y; r6 += v1.z; r7 += v1.w;
    }
    r0 += bias[n];

    float nm0 = fabsf(r0);
    float nm1 = sqrtf(r1 * r1 + r2 * r2 + r3 * r3);
    float nm2 = sqrtf(r4 * r4 + r5 * r5 + r6 * r6);
    float nm3 = fabsf(r7);

    const float* ap = a + (size_t)n * 4;
    float s0 = 1.f / (1.f + expf(-ap[0]));
    float s1 = 1.f / (1.f + expf(-ap[1]));
    float s2 = 1.f / (1.f + expf(-ap[2]));
    float s3 = 1.f / (1.f + expf(-ap[3]));

    float d0 = 1.f / (s0 * (nm0 - 1.f) + 1.f + EPS);
    float d1 = 1.f / (s1 * (nm1 - 1.f) + 1.f + EPS);
    float d2 = 1.f / (s2 * (nm2 - 1.f) + 1.f + EPS);
    float d3 = 1.f / (s3 * (nm3 - 1.f) + 1.f + EPS);

    float* o = &g_qk[side][off];
    *reinterpret_cast<float4*>(o)     = make_float4(r0 * d0, r1 * d1, r2 * d1, r3 * d1);
    *reinterpret_cast<float4*>(o + 4) = make_float4(r4 * d2, r5 * d2, r6 * d2, r7 * d3);
}

// ---------------------------------------------------------------------------
// Kernel B: pairwise geometric product, uniform-FMA + f32x2 over m-pairs.
// Even lanes use k, odd lanes use k' = k*(-e123) (identical FMA body).
// k' arrays are offset +64B in smem so even lanes hit banks 0-15 and odd
// lanes banks 16-31 within each wavefront -> conflict-free LDS.
// Stores use st.global.cs (streaming) -- output is write-once.
// ---------------------------------------------------------------------------
#define SKN 624

__device__ __forceinline__ void stcs4(float* p, float4 v) {
    asm volatile("st.global.cs.v4.f32 [%0], {%1, %2, %3, %4};"
                 :: "l"(p), "f"(v.x), "f"(v.y), "f"(v.z), "f"(v.w) : "memory");
}

__global__ __launch_bounds__(256) void gp_kernel(float* __restrict__ out)
{
    const int b  = blockIdx.y;
    const int m0 = blockIdx.x * 16;
    const int tid  = threadIdx.x;
    const int lane = tid & 31;
    const int w    = tid >> 5;

    // layout: [e_lo SKN][pad 4][o_lo SKN][pad 4][e_hi SKN][pad 4][o_hi SKN]
    __shared__ float4 skbuf[4 * SKN + 12];
    __shared__ float4 sq[16][2];

    float4* const e_lo = skbuf;
    float4* const o_lo = skbuf + SKN + 4;          // +64B -> bank shift 16
    float4* const e_hi = skbuf + 2 * SKN + 8;      // back to bank 0
    float4* const o_hi = skbuf + 3 * SKN + 12;     // +64B -> bank shift 16

    // stage k[b]: both variants
    const float* kbase = &g_qk[1][(size_t)b * S * 8];
    for (int r = tid; r < SKN; r += 256) {
        float4 kl = make_float4(0.f, 0.f, 0.f, 0.f), kh = kl;
        if (r < S) {
            kl = *reinterpret_cast<const float4*>(kbase + (size_t)r * 8);
            kh = *reinterpret_cast<const float4*>(kbase + (size_t)r * 8 + 4);
        }
        e_lo[r] = kl;
        e_hi[r] = kh;
        // k' = k*(-e123) = (k7, k6, -k5, k4, -k3, k2, -k1, -k0)
        o_lo[r] = make_float4( kh.w,  kh.z, -kh.y,  kh.x);
        o_hi[r] = make_float4(-kl.w,  kl.z, -kl.y, -kl.x);
    }
    // stage q rows m0..m0+15
    if (tid < 32) {
        int r = tid >> 1, half = tid & 1;
        int row = m0 + r;
        float4 v = make_float4(0.f, 0.f, 0.f, 0.f);
        if (row < S)
            v = *reinterpret_cast<const float4*>(&g_qk[0][((size_t)b * S + row) * 8 + half * 4]);
        sq[r][half] = v;
    }
    __syncthreads();

    const int m = m0 + 2 * w;
    if (m >= S) return;
    const bool has2 = (m + 1 < S);

    // pack q pairs (m in lo, m+1 in hi); row m+1 staged as zeros if OOB
    float4 qlA = sq[2 * w][0],     qhA = sq[2 * w][1];
    float4 qlB = sq[2 * w + 1][0], qhB = sq[2 * w + 1][1];
    u64 qp0 = pk2(qlA.x, qlB.x);
    u64 qp1 = pk2(qlA.y, qlB.y), qn1 = pk2(-qlA.y, -qlB.y);
    u64 qp2 = pk2(qlA.z, qlB.z), qn2 = pk2(-qlA.z, -qlB.z);
    u64 qp3 = pk2(qlA.w, qlB.w), qn3 = pk2(-qlA.w, -qlB.w);
    u64 qp4 = pk2(qhA.x, qhB.x), qn4 = pk2(-qhA.x, -qhB.x);
    u64 qp5 = pk2(qhA.y, qhB.y), qn5 = pk2(-qhA.y, -qhB.y);
    u64 qp6 = pk2(qhA.z, qhB.z), qn6 = pk2(-qhA.z, -qhB.z);
    u64 qp7 = pk2(qhA.w, qhB.w), qn7 = pk2(-qhA.w, -qhB.w);

    const int  jhalf = lane & 1;
    const int  nlane = lane >> 1;
    const float4* __restrict__ klp = jhalf ? o_lo : e_lo;
    const float4* __restrict__ khp = jhalf ? o_hi : e_hi;

    float* const rowA = out + (((size_t)b * S + m) * S) * 8 + jhalf * 4;
    float* const rowB = rowA + (size_t)S * 8;

    auto body = [&](int n) {
        float4 kl = klp[n];
        float4 kh = khp[n];
        u64 kd, o0, o1, o2, o3;
        kd = pk2(kl.x, kl.x);   // k0
        o0 = mul2(qp0, kd); o1 = mul2(qp1, kd); o2 = mul2(qp2, kd); o3 = mul2(qp3, kd);
        kd = pk2(kl.y, kl.y);   // k1
        o0 = fma2(qp1, kd, o0); o1 = fma2(qp0, kd, o1); o2 = fma2(qn4, kd, o2); o3 = fma2(qn5, kd, o3);
        kd = pk2(kl.z, kl.z);   // k2
        o0 = fma2(qp2, kd, o0); o1 = fma2(qp4, kd, o1); o2 = fma2(qp0, kd, o2); o3 = fma2(qn6, kd, o3);
        kd = pk2(kl.w, kl.w);   // k3
        o0 = fma2(qp3, kd, o0); o1 = fma2(qp5, kd, o1); o2 = fma2(qp6, kd, o2); o3 = fma2(qp0, kd, o3);
        kd = pk2(kh.x, kh.x);   // k4
        o0 = fma2(qn4, kd, o0); o1 = fma2(qn2, kd, o1); o2 = fma2(qp1, kd, o2); o3 = fma2(qn7, kd, o3);
        kd = pk2(kh.y, kh.y);   // k5
        o0 = fma2(qn5, kd, o0); o1 = fma2(qn3, kd, o1); o2 = fma2(qp7, kd, o2); o3 = fma2(qp1, kd, o3);
        kd = pk2(kh.z, kh.z);   // k6
        o0 = fma2(qn6, kd, o0); o1 = fma2(qn7, kd, o1); o2 = fma2(qn3, kd, o2); o3 = fma2(qp2, kd, o3);
        kd = pk2(kh.w, kh.w);   // k7
        o0 = fma2(qn7, kd, o0); o1 = fma2(qn6, kd, o1); o2 = fma2(qp5, kd, o2); o3 = fma2(qn4, kd, o3);

        float a0, b0, a1, b1, a2, b2, a3, b3;
        up2(o0, a0, b0); up2(o1, a1, b1); up2(o2, a2, b2); up2(o3, a3, b3);

        // even lanes: (o0..o3); odd lanes: results (o7,o6,-o5,o4) -> (o4..o7)=(r3,-r2,r1,r0)
        float4 vA = jhalf ? make_float4(a3, -a2, a1, a0) : make_float4(a0, a1, a2, a3);
        float4 vB = jhalf ? make_float4(b3, -b2, b1, b0) : make_float4(b0, b1, b2, b3);

        stcs4(rowA + (size_t)n * 8, vA);
        if (has2)
            stcs4(rowB + (size_t)n * 8, vB);
    };

    #pragma unroll 4
    for (int j = 0; j < 38; j++)
        body(j * 16 + nlane);
    {   // tail: n = 608 + nlane, valid while n < 618
        const int n = 608 + nlane;
        if (n < S) body(n);
    }
}

// ---------------------------------------------------------------------------
extern "C" void kernel_launch(void* const* d_in, const int* in_sizes, int n_in,
                              void* d_out, int out_size)
{
    const float* x  = (const float*)d_in[0];
    const float* qw = (const float*)d_in[1];
    const float* qb = (const float*)d_in[2];
    const float* kw = (const float*)d_in[3];
    const float* kb = (const float*)d_in[4];
    const float* a  = (const float*)d_in[5];
    float* out = (float*)d_out;

    dim3 gridA1((S + TNB - 1) / TNB, 8, 2);
    qk_partial_kernel<<<gridA1, 256>>>(x, qw, kw);

    int totalA2 = 2 * B * S;
    qk_finalize_kernel<<<(totalA2 + 255) / 256, 256>>>(qb, kb, a);

    dim3 gridB((S + 15) / 16, B);
    gp_kernel<<<gridB, 256>>>(out);
}